// round 1
// baseline (speedup 1.0000x reference)
#include <cuda_runtime.h>
#include <cstdint>

#define NN 50000
#define EE 800000
#define RR 6
#define FF 128
#define KTOT 1536   // 2 heads * R * F

// ---------------- scratch (static device globals; no allocations) ----------------
__device__ __align__(16) float g_aggN[RR * NN * FF];   // 153.6 MB: sum of node_h[src] per (rel,dst)
__device__ __align__(16) float g_deg[RR * NN];          // per (rel,dst) incoming degree
__device__ __align__(16) float g_c1[NN * RR];           // s1/(1+deg)
__device__ __align__(16) float g_c2[NN * RR];           // s2/(1+deg)
__device__ __align__(16) float g_v1[RR * FF];           // W[r] @ att1
__device__ __align__(16) float g_v2[RR * FF];           // W[r] @ att2
__device__ __align__(16) float g_B[KTOT * FF];          // [k][o]: rows 0..767 = W[r]@Wc1^T, 768..1535 = W[r]@Wc2^T (tf32-rounded)

__device__ __forceinline__ float tf32r(float x) {
    uint32_t u;
    asm("cvt.rna.tf32.f32 %0, %1;" : "=r"(u) : "f"(x));
    return __uint_as_float(u);
}

// ---------------- K0: precompute v1,v2 and fused B = W @ [Wc1^T | Wc2^T] ----------------
// grid = R*F blocks (one per (r,f) row of W), 128 threads (one per output o)
__global__ void precompute_kernel(const float* __restrict__ W,
                                  const float* __restrict__ att1,
                                  const float* __restrict__ att2,
                                  const float* __restrict__ Wc) {
    __shared__ float wrow[128];
    __shared__ float red1[128];
    __shared__ float red2[128];
    int rf = blockIdx.x;           // r*128 + f
    int o  = threadIdx.x;
    wrow[o] = W[rf * 128 + o];
    __syncthreads();

    // M1[rf][o] = sum_j W[r][f][j] * Wc[o][j];  M2 uses Wc[o][128+j]
    float m1 = 0.f, m2 = 0.f;
    const float* wc = Wc + o * 256;
#pragma unroll 8
    for (int j = 0; j < 128; j++) {
        float w = wrow[j];
        m1 += w * wc[j];
        m2 += w * wc[128 + j];
    }
    g_B[rf * 128 + o]          = tf32r(m1);
    g_B[(768 + rf) * 128 + o]  = tf32r(m2);

    // v1[rf] = dot(wrow, att1); v2[rf] = dot(wrow, att2)
    red1[o] = wrow[o] * att1[o];
    red2[o] = wrow[o] * att2[o];
    __syncthreads();
    for (int s = 64; s > 0; s >>= 1) {
        if (o < s) { red1[o] += red1[o + s]; red2[o] += red2[o + s]; }
        __syncthreads();
    }
    if (o == 0) { g_v1[rf] = red1[0]; g_v2[rf] = red2[0]; }
}

// ---------------- Kz: zero aggN + deg ----------------
__global__ void zero_kernel() {
    unsigned i = blockIdx.x * blockDim.x + threadIdx.x;
    float4 z = make_float4(0.f, 0.f, 0.f, 0.f);
    if (i < (unsigned)(RR * NN * FF / 4)) reinterpret_cast<float4*>(g_aggN)[i] = z;
    if (i < (unsigned)(RR * NN / 4))      reinterpret_cast<float4*>(g_deg)[i]  = z;
}

// ---------------- K2: edge scatter (32 threads per edge, float4 vector red) ----------------
__global__ void scatter_kernel(const float* __restrict__ node_h,
                               const int* __restrict__ esrc,
                               const int* __restrict__ edst,
                               const int* __restrict__ erel) {
    unsigned gid = blockIdx.x * blockDim.x + threadIdx.x;
    unsigned e = gid >> 5;
    unsigned q = gid & 31u;
    if (e >= EE) return;
    int src = esrc[e];
    int dst = edst[e];
    int rel = erel[e];
    float4 v = reinterpret_cast<const float4*>(node_h)[src * 32 + q];
    float* p = &g_aggN[((size_t)rel * NN + dst) * FF + q * 4];
    asm volatile("red.global.add.v4.f32 [%0], {%1,%2,%3,%4};"
                 :: "l"(p), "f"(v.x), "f"(v.y), "f"(v.z), "f"(v.w) : "memory");
    if (q == 0) atomicAdd(&g_deg[rel * NN + dst], 1.0f);
}

// ---------------- K3: per-node attention coefficients ----------------
// one warp per node: e{1,2}[r] = dot(aggN[r,n], v{1,2}[r]) / (1+deg); softmax over r; c = s/(1+deg)
__global__ void attn_kernel() {
    int warp = threadIdx.x >> 5;
    int n = blockIdx.x * 8 + warp;
    if (n >= NN) return;
    int l = threadIdx.x & 31;

    float e1[RR], e2[RR], dg[RR];
#pragma unroll
    for (int r = 0; r < RR; r++) {
        const float* a = &g_aggN[((size_t)r * NN + n) * FF];
        float d1 = 0.f, d2 = 0.f;
#pragma unroll
        for (int p = 0; p < 4; p++) {
            float x = a[l + p * 32];
            d1 += x * g_v1[r * 128 + l + p * 32];
            d2 += x * g_v2[r * 128 + l + p * 32];
        }
#pragma unroll
        for (int s = 16; s > 0; s >>= 1) {
            d1 += __shfl_xor_sync(0xffffffffu, d1, s);
            d2 += __shfl_xor_sync(0xffffffffu, d2, s);
        }
        dg[r] = 1.0f + g_deg[r * NN + n];
        e1[r] = d1 / dg[r];
        e2[r] = d2 / dg[r];
    }
    float m1 = e1[0], m2 = e2[0];
#pragma unroll
    for (int r = 1; r < RR; r++) { m1 = fmaxf(m1, e1[r]); m2 = fmaxf(m2, e2[r]); }
    float s1 = 0.f, s2 = 0.f;
#pragma unroll
    for (int r = 0; r < RR; r++) {
        e1[r] = __expf(e1[r] - m1); s1 += e1[r];
        e2[r] = __expf(e2[r] - m2); s2 += e2[r];
    }
    float i1 = 1.0f / s1, i2 = 1.0f / s2;
    if (l == 0) {
#pragma unroll
        for (int r = 0; r < RR; r++) {
            g_c1[n * RR + r] = e1[r] * i1 / dg[r];
            g_c2[n * RR + r] = e2[r] * i2 / dg[r];
        }
    }
}

// ---------------- K4: fused tf32 GEMM  h = A' @ g_B + 6*bc ----------------
// A'[n, k] (k in [0,1536)): src = k/768 selects c1/c2, r = (k%768)/128, f = k%128
// A'[n,k] = c_src[n,r] * aggN[r,n,f]
__device__ __forceinline__ void mma8(float d[4], float a0, float a1, float a2, float a3,
                                     float b0, float b1) {
    uint32_t A0 = __float_as_uint(a0), A1 = __float_as_uint(a1);
    uint32_t A2 = __float_as_uint(a2), A3 = __float_as_uint(a3);
    uint32_t B0 = __float_as_uint(b0), B1 = __float_as_uint(b1);
    asm volatile(
        "mma.sync.aligned.m16n8k8.row.col.f32.tf32.tf32.f32 "
        "{%0,%1,%2,%3},{%4,%5,%6,%7},{%8,%9},{%0,%1,%2,%3};"
        : "+f"(d[0]), "+f"(d[1]), "+f"(d[2]), "+f"(d[3])
        : "r"(A0), "r"(A1), "r"(A2), "r"(A3), "r"(B0), "r"(B1));
}

__global__ __launch_bounds__(128) void gemm_kernel(float* __restrict__ out,
                                                   const float* __restrict__ bc) {
    __shared__ __align__(16) float As[128 * 36];   // 128 rows x 32 k, pad stride 36
    __shared__ __align__(16) float Bs[32 * 132];   // 32 k x 128 o, pad stride 132

    int n0 = blockIdx.x * 128;
    int t = threadIdx.x;
    int warp = t >> 5, lane = t & 31;
    int wm = warp >> 1, wn = warp & 1;     // 2x2 warps, each 64x64
    int g = lane >> 2, tg = lane & 3;

    float acc[4][8][4];
#pragma unroll
    for (int mi = 0; mi < 4; mi++)
#pragma unroll
        for (int ni = 0; ni < 8; ni++)
#pragma unroll
            for (int j = 0; j < 4; j++) acc[mi][ni][j] = 0.f;

    for (int ch = 0; ch < 48; ch++) {
        int kg = ch * 32;
        int srcsel = (kg >= 768);
        int kr = kg - srcsel * 768;
        int r = kr >> 7;
        int f0 = kr & 127;

        // ---- load A tile: row t, 32 floats, scaled by c_src[n,r], tf32-rounded
        {
            int row = t;
            int n = n0 + row;
            float cs = 0.f;
            const float4* ap = nullptr;
            if (n < NN) {
                cs = (srcsel ? g_c2 : g_c1)[n * RR + r];
                ap = reinterpret_cast<const float4*>(&g_aggN[((size_t)r * NN + n) * FF + f0]);
            }
#pragma unroll
            for (int j = 0; j < 8; j++) {
                float4 v = make_float4(0.f, 0.f, 0.f, 0.f);
                if (n < NN) v = ap[j];
                v.x = tf32r(v.x * cs);
                v.y = tf32r(v.y * cs);
                v.z = tf32r(v.z * cs);
                v.w = tf32r(v.w * cs);
                *reinterpret_cast<float4*>(&As[row * 36 + j * 4]) = v;
            }
        }
        // ---- load B tile (already tf32-rounded)
        {
            int kk = t >> 2;
            int cseg = (t & 3) * 32;
            const float4* bp = reinterpret_cast<const float4*>(&g_B[(kg + kk) * 128 + cseg]);
#pragma unroll
            for (int j = 0; j < 8; j++)
                *reinterpret_cast<float4*>(&Bs[kk * 132 + cseg + j * 4]) = bp[j];
        }
        __syncthreads();

#pragma unroll
        for (int ks = 0; ks < 4; ks++) {
            float a[4][4];
            float b[8][2];
#pragma unroll
            for (int mi = 0; mi < 4; mi++) {
                int r0 = wm * 64 + mi * 16 + g;
                a[mi][0] = As[r0 * 36 + ks * 8 + tg];
                a[mi][1] = As[(r0 + 8) * 36 + ks * 8 + tg];
                a[mi][2] = As[r0 * 36 + ks * 8 + tg + 4];
                a[mi][3] = As[(r0 + 8) * 36 + ks * 8 + tg + 4];
            }
#pragma unroll
            for (int ni = 0; ni < 8; ni++) {
                int cc = wn * 64 + ni * 8 + g;
                b[ni][0] = Bs[(ks * 8 + tg) * 132 + cc];
                b[ni][1] = Bs[(ks * 8 + tg + 4) * 132 + cc];
            }
#pragma unroll
            for (int mi = 0; mi < 4; mi++)
#pragma unroll
                for (int ni = 0; ni < 8; ni++)
                    mma8(acc[mi][ni], a[mi][0], a[mi][1], a[mi][2], a[mi][3],
                         b[ni][0], b[ni][1]);
        }
        __syncthreads();
    }

    // ---- epilogue: + 6*bc, write h
#pragma unroll
    for (int mi = 0; mi < 4; mi++) {
        int r0 = n0 + wm * 64 + mi * 16 + g;
#pragma unroll
        for (int ni = 0; ni < 8; ni++) {
            int c0 = wn * 64 + ni * 8 + tg * 2;
            float b0 = 6.0f * bc[c0];
            float b1 = 6.0f * bc[c0 + 1];
            if (r0 < NN) {
                float2 v = make_float2(acc[mi][ni][0] + b0, acc[mi][ni][1] + b1);
                *reinterpret_cast<float2*>(&out[(size_t)r0 * FF + c0]) = v;
            }
            if (r0 + 8 < NN) {
                float2 v = make_float2(acc[mi][ni][2] + b0, acc[mi][ni][3] + b1);
                *reinterpret_cast<float2*>(&out[(size_t)(r0 + 8) * FF + c0]) = v;
            }
        }
    }
}

// ---------------- launch ----------------
extern "C" void kernel_launch(void* const* d_in, const int* in_sizes, int n_in,
                              void* d_out, int out_size) {
    const float* node_h = (const float*)d_in[0];
    const float* W      = (const float*)d_in[1];
    const float* att1   = (const float*)d_in[2];
    const float* att2   = (const float*)d_in[3];
    const float* Wc     = (const float*)d_in[4];
    const float* bc     = (const float*)d_in[5];
    const int*   esrc   = (const int*)d_in[6];
    const int*   edst   = (const int*)d_in[7];
    const int*   erel   = (const int*)d_in[8];
    float* out = (float*)d_out;

    precompute_kernel<<<RR * FF, 128>>>(W, att1, att2, Wc);
    zero_kernel<<<(RR * NN * FF / 4 + 255) / 256, 256>>>();
    scatter_kernel<<<(EE * 32) / 256, 256>>>(node_h, esrc, edst, erel);
    attn_kernel<<<(NN + 7) / 8, 256>>>();
    gemm_kernel<<<(NN + 127) / 128, 128>>>(out, bc);

    // pass-through second output: weight
    if (out_size >= NN * FF + RR * FF * FF) {
        cudaMemcpyAsync(out + (size_t)NN * FF, W,
                        sizeof(float) * RR * FF * FF, cudaMemcpyDeviceToDevice, 0);
    }
}

// round 2
// speedup vs baseline: 1.1274x; 1.1274x over previous
#include <cuda_runtime.h>
#include <cstdint>

#define NN 50000
#define EE 800000
#define RR 6
#define FF 128

// ---------------- scratch (static device globals; no allocations) ----------------
__device__ __align__(16) float g_aggN[RR * NN * FF];   // 153.6 MB: sum of node_h[src] per (rel,dst)
__device__ __align__(16) float g_deg[RR * NN];          // per (rel,dst) incoming degree
__device__ __align__(16) float g_c1[NN * RR];           // s1/(1+deg)
__device__ __align__(16) float g_c2[NN * RR];           // s2/(1+deg)
__device__ __align__(16) float g_v1[RR * FF];           // W[r] @ att1
__device__ __align__(16) float g_v2[RR * FF];           // W[r] @ att2
__device__ __align__(16) float g_B[2 * RR * FF * FF];   // rows 0..767 = W[r]@Wc1^T, 768..1535 = W[r]@Wc2^T (tf32)

__device__ __forceinline__ float tf32r(float x) {
    uint32_t u;
    asm("cvt.rna.tf32.f32 %0, %1;" : "=r"(u) : "f"(x));
    return __uint_as_float(u);
}

__device__ __forceinline__ void cpa16(float* dst_smem, const float* src) {
    uint32_t d = (uint32_t)__cvta_generic_to_shared(dst_smem);
    asm volatile("cp.async.cg.shared.global [%0], [%1], 16;" :: "r"(d), "l"(src));
}

// ---------------- K0: precompute v1,v2 and fused B = W @ [Wc1^T | Wc2^T] ----------------
__global__ void precompute_kernel(const float* __restrict__ W,
                                  const float* __restrict__ att1,
                                  const float* __restrict__ att2,
                                  const float* __restrict__ Wc) {
    __shared__ float wrow[128];
    __shared__ float red1[128];
    __shared__ float red2[128];
    int rf = blockIdx.x;           // r*128 + f
    int o  = threadIdx.x;
    wrow[o] = W[rf * 128 + o];
    __syncthreads();

    float m1 = 0.f, m2 = 0.f;
    const float* wc = Wc + o * 256;
#pragma unroll 8
    for (int j = 0; j < 128; j++) {
        float w = wrow[j];
        m1 += w * wc[j];
        m2 += w * wc[128 + j];
    }
    g_B[rf * 128 + o]          = tf32r(m1);
    g_B[(768 + rf) * 128 + o]  = tf32r(m2);

    red1[o] = wrow[o] * att1[o];
    red2[o] = wrow[o] * att2[o];
    __syncthreads();
    for (int s = 64; s > 0; s >>= 1) {
        if (o < s) { red1[o] += red1[o + s]; red2[o] += red2[o + s]; }
        __syncthreads();
    }
    if (o == 0) { g_v1[rf] = red1[0]; g_v2[rf] = red2[0]; }
}

// ---------------- zero one relation-pair slice (keeps lines L2-resident for the scatter pass) ----
__global__ void zero_pass_kernel(int p) {
    unsigned i = blockIdx.x * blockDim.x + threadIdx.x;
    float4 z = make_float4(0.f, 0.f, 0.f, 0.f);
    size_t aggBase = (size_t)p * 2 * NN * (FF / 4);
    if (i < (unsigned)(2 * NN * FF / 4)) reinterpret_cast<float4*>(g_aggN)[aggBase + i] = z;
    if (i < (unsigned)(2 * NN / 4))
        reinterpret_cast<float4*>(g_deg)[(size_t)p * 2 * NN / 4 + i] = z;
}

// ---------------- edge scatter for one relation pair ----------------
__global__ void scatter_pass_kernel(const float* __restrict__ node_h,
                                    const int* __restrict__ esrc,
                                    const int* __restrict__ edst,
                                    const int* __restrict__ erel,
                                    int pass) {
    unsigned gid = blockIdx.x * blockDim.x + threadIdx.x;
    unsigned e = gid >> 5;
    unsigned q = gid & 31u;
    if (e >= EE) return;
    int rel = erel[e];
    if ((rel >> 1) != pass) return;   // this pass handles rels {2p, 2p+1}
    int src = esrc[e];
    int dst = edst[e];
    float4 v = reinterpret_cast<const float4*>(node_h)[src * 32 + q];
    float* p = &g_aggN[((size_t)rel * NN + dst) * FF + q * 4];
    asm volatile("red.global.add.v4.f32 [%0], {%1,%2,%3,%4};"
                 :: "l"(p), "f"(v.x), "f"(v.y), "f"(v.z), "f"(v.w) : "memory");
    if (q == 0) atomicAdd(&g_deg[rel * NN + dst], 1.0f);
}

// ---------------- K3: per-node attention coefficients ----------------
__global__ void attn_kernel() {
    int warp = threadIdx.x >> 5;
    int n = blockIdx.x * 8 + warp;
    if (n >= NN) return;
    int l = threadIdx.x & 31;

    float e1[RR], e2[RR], dg[RR];
#pragma unroll
    for (int r = 0; r < RR; r++) {
        const float* a = &g_aggN[((size_t)r * NN + n) * FF];
        float d1 = 0.f, d2 = 0.f;
#pragma unroll
        for (int p = 0; p < 4; p++) {
            float x = a[l + p * 32];
            d1 += x * g_v1[r * 128 + l + p * 32];
            d2 += x * g_v2[r * 128 + l + p * 32];
        }
#pragma unroll
        for (int s = 16; s > 0; s >>= 1) {
            d1 += __shfl_xor_sync(0xffffffffu, d1, s);
            d2 += __shfl_xor_sync(0xffffffffu, d2, s);
        }
        dg[r] = 1.0f + g_deg[r * NN + n];
        e1[r] = d1 / dg[r];
        e2[r] = d2 / dg[r];
    }
    float m1 = e1[0], m2 = e2[0];
#pragma unroll
    for (int r = 1; r < RR; r++) { m1 = fmaxf(m1, e1[r]); m2 = fmaxf(m2, e2[r]); }
    float s1 = 0.f, s2 = 0.f;
#pragma unroll
    for (int r = 0; r < RR; r++) {
        e1[r] = __expf(e1[r] - m1); s1 += e1[r];
        e2[r] = __expf(e2[r] - m2); s2 += e2[r];
    }
    float i1 = 1.0f / s1, i2 = 1.0f / s2;
    if (l == 0) {
#pragma unroll
        for (int r = 0; r < RR; r++) {
            g_c1[n * RR + r] = e1[r] * i1 / dg[r];
            g_c2[n * RR + r] = e2[r] * i2 / dg[r];
        }
    }
}

// ---------------- K4: per-relation tf32 GEMM with post-scaled accumulation ----------------
// For each r: P_h = tf32(agg[r,·]) @ M_h[r]  (K=128, h=0,1);  facc += c_h[n,r] * P_h
__device__ __forceinline__ void mma8(float d[4], float a0, float a1, float a2, float a3,
                                     float b0, float b1) {
    uint32_t A0 = __float_as_uint(a0), A1 = __float_as_uint(a1);
    uint32_t A2 = __float_as_uint(a2), A3 = __float_as_uint(a3);
    uint32_t B0 = __float_as_uint(b0), B1 = __float_as_uint(b1);
    asm volatile(
        "mma.sync.aligned.m16n8k8.row.col.f32.tf32.tf32.f32 "
        "{%0,%1,%2,%3},{%4,%5,%6,%7},{%8,%9},{%0,%1,%2,%3};"
        : "+f"(d[0]), "+f"(d[1]), "+f"(d[2]), "+f"(d[3])
        : "r"(A0), "r"(A1), "r"(A2), "r"(A3), "r"(B0), "r"(B1));
}

#define AS_STRIDE 132
#define BS_STRIDE 132
#define BS_BUF (32 * BS_STRIDE)

__global__ __launch_bounds__(256, 1) void gemm_kernel(float* __restrict__ out,
                                                      const float* __restrict__ bc) {
    extern __shared__ float sm[];
    float* As = sm;                    // [128][132]
    float* Bsm = sm + 128 * AS_STRIDE; // [2][32][132]

    int n0 = blockIdx.x * 128;
    int t = threadIdx.x;
    int warp = t >> 5, lane = t & 31;
    int wm = warp >> 1, wn = warp & 1;   // 4x2 warps; warp tile 32 rows x 64 cols
    int g = lane >> 2, tg = lane & 3;

    float facc[2][8][4];
#pragma unroll
    for (int mi = 0; mi < 2; mi++)
#pragma unroll
        for (int ni = 0; ni < 8; ni++)
#pragma unroll
            for (int j = 0; j < 4; j++) facc[mi][ni][j] = 0.f;

    for (int r = 0; r < RR; r++) {
        // ---- load A_r tile [128 x 128], tf32-rounded, unscaled
        {
            const float* base = g_aggN + ((size_t)r * NN + n0) * FF;
#pragma unroll
            for (int j = 0; j < 16; j++) {
                int lin = t + 256 * j;                 // 0..4095
                int row = lin >> 5;
                int c4 = (lin & 31) * 4;
                float4 v = make_float4(0.f, 0.f, 0.f, 0.f);
                if (n0 + row < NN) v = *reinterpret_cast<const float4*>(base + (size_t)row * FF + c4);
                v.x = tf32r(v.x); v.y = tf32r(v.y); v.z = tf32r(v.z); v.w = tf32r(v.w);
                *reinterpret_cast<float4*>(As + row * AS_STRIDE + c4) = v;
            }
        }
        // ---- prefetch first B chunk (head 0, kc 0)
        {
            const float* bsrc = g_B + (size_t)(r * 128) * 128;
#pragma unroll
            for (int j = 0; j < 4; j++) {
                int lin = t + 256 * j;
                int row = lin >> 5;
                int c4 = (lin & 31) * 4;
                cpa16(Bsm + row * BS_STRIDE + c4, bsrc + row * 128 + c4);
            }
            asm volatile("cp.async.commit_group;" ::: "memory");
        }

        float acc[2][8][4];
#pragma unroll
        for (int mi = 0; mi < 2; mi++)
#pragma unroll
            for (int ni = 0; ni < 8; ni++)
#pragma unroll
                for (int j = 0; j < 4; j++) acc[mi][ni][j] = 0.f;

        for (int tt = 0; tt < 8; tt++) {       // tt = head*4 + kc
            int buf = tt & 1;
            if (tt + 1 < 8) {
                int head = (tt + 1) >> 2, kc = (tt + 1) & 3;
                const float* bsrc = g_B + (size_t)(head * 768 + r * 128 + kc * 32) * 128;
#pragma unroll
                for (int j = 0; j < 4; j++) {
                    int lin = t + 256 * j;
                    int row = lin >> 5;
                    int c4 = (lin & 31) * 4;
                    cpa16(Bsm + (buf ^ 1) * BS_BUF + row * BS_STRIDE + c4, bsrc + row * 128 + c4);
                }
                asm volatile("cp.async.commit_group;" ::: "memory");
                asm volatile("cp.async.wait_group 1;" ::: "memory");
            } else {
                asm volatile("cp.async.wait_group 0;" ::: "memory");
            }
            __syncthreads();

            int kbase = (tt & 3) * 32;
            const float* Bp = Bsm + buf * BS_BUF;
#pragma unroll
            for (int ks = 0; ks < 4; ks++) {
                float a[2][4];
#pragma unroll
                for (int mi = 0; mi < 2; mi++) {
                    int rrow = wm * 32 + mi * 16 + g;
                    const float* ap = As + rrow * AS_STRIDE + kbase + ks * 8;
                    a[mi][0] = ap[tg];
                    a[mi][1] = ap[8 * AS_STRIDE + tg];
                    a[mi][2] = ap[tg + 4];
                    a[mi][3] = ap[8 * AS_STRIDE + tg + 4];
                }
                float b[8][2];
#pragma unroll
                for (int ni = 0; ni < 8; ni++) {
                    int cc = wn * 64 + ni * 8 + g;
                    b[ni][0] = Bp[(ks * 8 + tg) * BS_STRIDE + cc];
                    b[ni][1] = Bp[(ks * 8 + tg + 4) * BS_STRIDE + cc];
                }
#pragma unroll
                for (int mi = 0; mi < 2; mi++)
#pragma unroll
                    for (int ni = 0; ni < 8; ni++)
                        mma8(acc[mi][ni], a[mi][0], a[mi][1], a[mi][2], a[mi][3],
                             b[ni][0], b[ni][1]);
            }
            __syncthreads();

            if (tt == 3 || tt == 7) {
                int head = tt >> 2;
                const float* carr = head ? g_c2 : g_c1;
#pragma unroll
                for (int mi = 0; mi < 2; mi++) {
                    int ra = n0 + wm * 32 + mi * 16 + g;
                    int rb = ra + 8;
                    float ca = (ra < NN) ? carr[ra * RR + r] : 0.f;
                    float cb = (rb < NN) ? carr[rb * RR + r] : 0.f;
#pragma unroll
                    for (int ni = 0; ni < 8; ni++) {
                        facc[mi][ni][0] += ca * acc[mi][ni][0];
                        facc[mi][ni][1] += ca * acc[mi][ni][1];
                        facc[mi][ni][2] += cb * acc[mi][ni][2];
                        facc[mi][ni][3] += cb * acc[mi][ni][3];
                        acc[mi][ni][0] = 0.f; acc[mi][ni][1] = 0.f;
                        acc[mi][ni][2] = 0.f; acc[mi][ni][3] = 0.f;
                    }
                }
            }
        }
    }

    // ---- epilogue: + 6*bc
#pragma unroll
    for (int mi = 0; mi < 2; mi++) {
        int ra = n0 + wm * 32 + mi * 16 + g;
#pragma unroll
        for (int ni = 0; ni < 8; ni++) {
            int c0 = wn * 64 + ni * 8 + tg * 2;
            float b0 = 6.0f * bc[c0];
            float b1 = 6.0f * bc[c0 + 1];
            if (ra < NN) {
                float2 v = make_float2(facc[mi][ni][0] + b0, facc[mi][ni][1] + b1);
                *reinterpret_cast<float2*>(&out[(size_t)ra * FF + c0]) = v;
            }
            if (ra + 8 < NN) {
                float2 v = make_float2(facc[mi][ni][2] + b0, facc[mi][ni][3] + b1);
                *reinterpret_cast<float2*>(&out[(size_t)(ra + 8) * FF + c0]) = v;
            }
        }
    }
}

// ---------------- launch ----------------
extern "C" void kernel_launch(void* const* d_in, const int* in_sizes, int n_in,
                              void* d_out, int out_size) {
    const float* node_h = (const float*)d_in[0];
    const float* W      = (const float*)d_in[1];
    const float* att1   = (const float*)d_in[2];
    const float* att2   = (const float*)d_in[3];
    const float* Wc     = (const float*)d_in[4];
    const float* bc     = (const float*)d_in[5];
    const int*   esrc   = (const int*)d_in[6];
    const int*   edst   = (const int*)d_in[7];
    const int*   erel   = (const int*)d_in[8];
    float* out = (float*)d_out;

    static int smem_set = 0;
    const int gemm_smem = (128 * AS_STRIDE + 2 * BS_BUF) * sizeof(float);  // ~101 KB
    if (!smem_set) {
        cudaFuncSetAttribute(gemm_kernel, cudaFuncAttributeMaxDynamicSharedMemorySize, gemm_smem);
        smem_set = 1;
    }

    precompute_kernel<<<RR * FF, 128>>>(W, att1, att2, Wc);
    for (int p = 0; p < 3; p++) {
        zero_pass_kernel<<<(2 * NN * FF / 4 + 255) / 256, 256>>>(p);
        scatter_pass_kernel<<<(EE * 32) / 256, 256>>>(node_h, esrc, edst, erel, p);
    }
    attn_kernel<<<(NN + 7) / 8, 256>>>();
    gemm_kernel<<<(NN + 127) / 128, 256, gemm_smem>>>(out, bc);

    // pass-through second output: weight
    if (out_size >= NN * FF + RR * FF * FF) {
        cudaMemcpyAsync(out + (size_t)NN * FF, W,
                        sizeof(float) * RR * FF * FF, cudaMemcpyDeviceToDevice, 0);
    }
}

// round 3
// speedup vs baseline: 1.3058x; 1.1582x over previous
#include <cuda_runtime.h>
#include <cstdint>

#define NN 50000
#define EE 800000
#define RR 6
#define FF 128
#define SEG (RR * NN)          // 300000 (rel,dst) segments

// ---------------- scratch (static device globals; no allocations) ----------------
__device__ __align__(16) float g_aggN[RR * NN * FF];   // 153.6 MB
__device__ __align__(16) float g_c1[NN * RR];
__device__ __align__(16) float g_c2[NN * RR];
__device__ __align__(16) float g_v1[RR * FF];
__device__ __align__(16) float g_v2[RR * FF];
__device__ __align__(16) float g_B[2 * RR * FF * FF];  // tf32-rounded fused B

__device__ __align__(16) int g_cnt[SEG];               // per-segment degree
__device__ __align__(16) int g_off[SEG];               // exclusive offsets
__device__ __align__(16) int g_cur[SEG];               // fill cursors
__device__ __align__(16) int g_bsum[1024];             // scan partials
__device__ __align__(16) int g_src_sorted[EE];         // src ids sorted by (rel,dst)

__device__ __forceinline__ float tf32r(float x) {
    uint32_t u;
    asm("cvt.rna.tf32.f32 %0, %1;" : "=r"(u) : "f"(x));
    return __uint_as_float(u);
}

__device__ __forceinline__ void cpa16(float* dst_smem, const float* src) {
    uint32_t d = (uint32_t)__cvta_generic_to_shared(dst_smem);
    asm volatile("cp.async.cg.shared.global [%0], [%1], 16;" :: "r"(d), "l"(src));
}

// ---------------- K0: precompute v1,v2 and fused B = W @ [Wc1^T | Wc2^T] ----------------
__global__ void precompute_kernel(const float* __restrict__ W,
                                  const float* __restrict__ att1,
                                  const float* __restrict__ att2,
                                  const float* __restrict__ Wc) {
    __shared__ float wrow[128];
    __shared__ float red1[128];
    __shared__ float red2[128];
    int rf = blockIdx.x;
    int o  = threadIdx.x;
    wrow[o] = W[rf * 128 + o];
    __syncthreads();

    float m1 = 0.f, m2 = 0.f;
    const float* wc = Wc + o * 256;
#pragma unroll 8
    for (int j = 0; j < 128; j++) {
        float w = wrow[j];
        m1 += w * wc[j];
        m2 += w * wc[128 + j];
    }
    g_B[rf * 128 + o]          = tf32r(m1);
    g_B[(768 + rf) * 128 + o]  = tf32r(m2);

    red1[o] = wrow[o] * att1[o];
    red2[o] = wrow[o] * att2[o];
    __syncthreads();
    for (int s = 64; s > 0; s >>= 1) {
        if (o < s) { red1[o] += red1[o + s]; red2[o] += red2[o + s]; }
        __syncthreads();
    }
    if (o == 0) { g_v1[rf] = red1[0]; g_v2[rf] = red2[0]; }
}

// ---------------- CSR build ----------------
__global__ void zero_cnt_kernel() {
    int i = blockIdx.x * blockDim.x + threadIdx.x;
    if (i < SEG) g_cnt[i] = 0;
}

__global__ void hist_kernel(const int* __restrict__ edst, const int* __restrict__ erel) {
    int i = blockIdx.x * blockDim.x + threadIdx.x;
    if (i >= EE) return;
    atomicAdd(&g_cnt[erel[i] * NN + edst[i]], 1);
}

// scan1: per-block (512) inclusive scan; store per-element exclusive + block sums
__global__ void scan1_kernel() {
    __shared__ int sm[512];
    int tid = threadIdx.x;
    int idx = blockIdx.x * 512 + tid;
    int v = (idx < SEG) ? g_cnt[idx] : 0;
    sm[tid] = v;
    __syncthreads();
#pragma unroll
    for (int s = 1; s < 512; s <<= 1) {
        int add = (tid >= s) ? sm[tid - s] : 0;
        __syncthreads();
        sm[tid] += add;
        __syncthreads();
    }
    int incl = sm[tid];
    if (idx < SEG) g_off[idx] = incl - v;
    if (tid == 511) g_bsum[blockIdx.x] = incl;
}

// scan2: single block exclusive scan of block sums (<=1024)
__global__ void scan2_kernel(int nblk) {
    __shared__ int sm[1024];
    int tid = threadIdx.x;
    int v = (tid < nblk) ? g_bsum[tid] : 0;
    sm[tid] = v;
    __syncthreads();
#pragma unroll
    for (int s = 1; s < 1024; s <<= 1) {
        int add = (tid >= s) ? sm[tid - s] : 0;
        __syncthreads();
        sm[tid] += add;
        __syncthreads();
    }
    if (tid < nblk) g_bsum[tid] = sm[tid] - v;
}

__global__ void scan3_kernel() {
    int idx = blockIdx.x * blockDim.x + threadIdx.x;
    if (idx >= SEG) return;
    int o = g_off[idx] + g_bsum[idx >> 9];
    g_off[idx] = o;
    g_cur[idx] = o;
}

__global__ void permute_kernel(const int* __restrict__ esrc,
                               const int* __restrict__ edst,
                               const int* __restrict__ erel) {
    int i = blockIdx.x * blockDim.x + threadIdx.x;
    if (i >= EE) return;
    int key = erel[i] * NN + edst[i];
    int pos = atomicAdd(&g_cur[key], 1);
    g_src_sorted[pos] = esrc[i];
}

// ---------------- fused gather + attention ----------------
// one block (128 threads) per dst node: sum node_h rows per relation,
// write aggN once (streaming), compute attention coefficients in-block.
__global__ __launch_bounds__(128) void gather_attn_kernel(const float* __restrict__ node_h) {
    int n = blockIdx.x;
    int t = threadIdx.x;
    __shared__ float s1s[RR][4];
    __shared__ float s2s[RR][4];
    __shared__ float sdg[RR];

#pragma unroll
    for (int r = 0; r < RR; r++) {
        int key = r * NN + n;
        int off = g_off[key];
        int deg = g_cnt[key];
        float acc = 0.f;
        int e = 0;
        for (; e + 4 <= deg; e += 4) {
            int i0 = g_src_sorted[off + e];
            int i1 = g_src_sorted[off + e + 1];
            int i2 = g_src_sorted[off + e + 2];
            int i3 = g_src_sorted[off + e + 3];
            float x0 = __ldg(&node_h[(size_t)i0 * FF + t]);
            float x1 = __ldg(&node_h[(size_t)i1 * FF + t]);
            float x2 = __ldg(&node_h[(size_t)i2 * FF + t]);
            float x3 = __ldg(&node_h[(size_t)i3 * FF + t]);
            acc += (x0 + x1) + (x2 + x3);
        }
        for (; e < deg; e++)
            acc += __ldg(&node_h[(size_t)g_src_sorted[off + e] * FF + t]);

        g_aggN[(size_t)key * FF + t] = acc;

        float p1 = acc * g_v1[r * FF + t];
        float p2 = acc * g_v2[r * FF + t];
#pragma unroll
        for (int s = 16; s > 0; s >>= 1) {
            p1 += __shfl_xor_sync(0xffffffffu, p1, s);
            p2 += __shfl_xor_sync(0xffffffffu, p2, s);
        }
        if ((t & 31) == 0) { s1s[r][t >> 5] = p1; s2s[r][t >> 5] = p2; }
        if (t == 0) sdg[r] = 1.0f + (float)deg;
    }
    __syncthreads();

    if (t == 0) {
        float e1[RR], e2[RR];
#pragma unroll
        for (int r = 0; r < RR; r++) {
            float d1 = (s1s[r][0] + s1s[r][1]) + (s1s[r][2] + s1s[r][3]);
            float d2 = (s2s[r][0] + s2s[r][1]) + (s2s[r][2] + s2s[r][3]);
            e1[r] = d1 / sdg[r];
            e2[r] = d2 / sdg[r];
        }
        float m1 = e1[0], m2 = e2[0];
#pragma unroll
        for (int r = 1; r < RR; r++) { m1 = fmaxf(m1, e1[r]); m2 = fmaxf(m2, e2[r]); }
        float s1 = 0.f, s2 = 0.f;
#pragma unroll
        for (int r = 0; r < RR; r++) {
            e1[r] = __expf(e1[r] - m1); s1 += e1[r];
            e2[r] = __expf(e2[r] - m2); s2 += e2[r];
        }
        float i1 = 1.0f / s1, i2 = 1.0f / s2;
#pragma unroll
        for (int r = 0; r < RR; r++) {
            g_c1[n * RR + r] = e1[r] * i1 / sdg[r];
            g_c2[n * RR + r] = e2[r] * i2 / sdg[r];
        }
    }
}

// ---------------- K4: per-relation tf32 GEMM with post-scaled accumulation ----------------
__device__ __forceinline__ void mma8(float d[4], float a0, float a1, float a2, float a3,
                                     float b0, float b1) {
    uint32_t A0 = __float_as_uint(a0), A1 = __float_as_uint(a1);
    uint32_t A2 = __float_as_uint(a2), A3 = __float_as_uint(a3);
    uint32_t B0 = __float_as_uint(b0), B1 = __float_as_uint(b1);
    asm volatile(
        "mma.sync.aligned.m16n8k8.row.col.f32.tf32.tf32.f32 "
        "{%0,%1,%2,%3},{%4,%5,%6,%7},{%8,%9},{%0,%1,%2,%3};"
        : "+f"(d[0]), "+f"(d[1]), "+f"(d[2]), "+f"(d[3])
        : "r"(A0), "r"(A1), "r"(A2), "r"(A3), "r"(B0), "r"(B1));
}

#define AS_STRIDE 132
#define BS_STRIDE 132
#define BS_BUF (32 * BS_STRIDE)

__global__ __launch_bounds__(256, 1) void gemm_kernel(float* __restrict__ out,
                                                      const float* __restrict__ bc) {
    extern __shared__ float sm[];
    float* As = sm;
    float* Bsm = sm + 128 * AS_STRIDE;

    int n0 = blockIdx.x * 128;
    int t = threadIdx.x;
    int warp = t >> 5, lane = t & 31;
    int wm = warp >> 1, wn = warp & 1;
    int g = lane >> 2, tg = lane & 3;

    float facc[2][8][4];
#pragma unroll
    for (int mi = 0; mi < 2; mi++)
#pragma unroll
        for (int ni = 0; ni < 8; ni++)
#pragma unroll
            for (int j = 0; j < 4; j++) facc[mi][ni][j] = 0.f;

    for (int r = 0; r < RR; r++) {
        {
            const float* base = g_aggN + ((size_t)r * NN + n0) * FF;
#pragma unroll
            for (int j = 0; j < 16; j++) {
                int lin = t + 256 * j;
                int row = lin >> 5;
                int c4 = (lin & 31) * 4;
                float4 v = make_float4(0.f, 0.f, 0.f, 0.f);
                if (n0 + row < NN) v = *reinterpret_cast<const float4*>(base + (size_t)row * FF + c4);
                v.x = tf32r(v.x); v.y = tf32r(v.y); v.z = tf32r(v.z); v.w = tf32r(v.w);
                *reinterpret_cast<float4*>(As + row * AS_STRIDE + c4) = v;
            }
        }
        {
            const float* bsrc = g_B + (size_t)(r * 128) * 128;
#pragma unroll
            for (int j = 0; j < 4; j++) {
                int lin = t + 256 * j;
                int row = lin >> 5;
                int c4 = (lin & 31) * 4;
                cpa16(Bsm + row * BS_STRIDE + c4, bsrc + row * 128 + c4);
            }
            asm volatile("cp.async.commit_group;" ::: "memory");
        }

        float acc[2][8][4];
#pragma unroll
        for (int mi = 0; mi < 2; mi++)
#pragma unroll
            for (int ni = 0; ni < 8; ni++)
#pragma unroll
                for (int j = 0; j < 4; j++) acc[mi][ni][j] = 0.f;

        for (int tt = 0; tt < 8; tt++) {
            int buf = tt & 1;
            if (tt + 1 < 8) {
                int head = (tt + 1) >> 2, kc = (tt + 1) & 3;
                const float* bsrc = g_B + (size_t)(head * 768 + r * 128 + kc * 32) * 128;
#pragma unroll
                for (int j = 0; j < 4; j++) {
                    int lin = t + 256 * j;
                    int row = lin >> 5;
                    int c4 = (lin & 31) * 4;
                    cpa16(Bsm + (buf ^ 1) * BS_BUF + row * BS_STRIDE + c4, bsrc + row * 128 + c4);
                }
                asm volatile("cp.async.commit_group;" ::: "memory");
                asm volatile("cp.async.wait_group 1;" ::: "memory");
            } else {
                asm volatile("cp.async.wait_group 0;" ::: "memory");
            }
            __syncthreads();

            int kbase = (tt & 3) * 32;
            const float* Bp = Bsm + buf * BS_BUF;
#pragma unroll
            for (int ks = 0; ks < 4; ks++) {
                float a[2][4];
#pragma unroll
                for (int mi = 0; mi < 2; mi++) {
                    int rrow = wm * 32 + mi * 16 + g;
                    const float* ap = As + rrow * AS_STRIDE + kbase + ks * 8;
                    a[mi][0] = ap[tg];
                    a[mi][1] = ap[8 * AS_STRIDE + tg];
                    a[mi][2] = ap[tg + 4];
                    a[mi][3] = ap[8 * AS_STRIDE + tg + 4];
                }
                float b[8][2];
#pragma unroll
                for (int ni = 0; ni < 8; ni++) {
                    int cc = wn * 64 + ni * 8 + g;
                    b[ni][0] = Bp[(ks * 8 + tg) * BS_STRIDE + cc];
                    b[ni][1] = Bp[(ks * 8 + tg + 4) * BS_STRIDE + cc];
                }
#pragma unroll
                for (int mi = 0; mi < 2; mi++)
#pragma unroll
                    for (int ni = 0; ni < 8; ni++)
                        mma8(acc[mi][ni], a[mi][0], a[mi][1], a[mi][2], a[mi][3],
                             b[ni][0], b[ni][1]);
            }
            __syncthreads();

            if (tt == 3 || tt == 7) {
                int head = tt >> 2;
                const float* carr = head ? g_c2 : g_c1;
#pragma unroll
                for (int mi = 0; mi < 2; mi++) {
                    int ra = n0 + wm * 32 + mi * 16 + g;
                    int rb = ra + 8;
                    float ca = (ra < NN) ? carr[ra * RR + r] : 0.f;
                    float cb = (rb < NN) ? carr[rb * RR + r] : 0.f;
#pragma unroll
                    for (int ni = 0; ni < 8; ni++) {
                        facc[mi][ni][0] += ca * acc[mi][ni][0];
                        facc[mi][ni][1] += ca * acc[mi][ni][1];
                        facc[mi][ni][2] += cb * acc[mi][ni][2];
                        facc[mi][ni][3] += cb * acc[mi][ni][3];
                        acc[mi][ni][0] = 0.f; acc[mi][ni][1] = 0.f;
                        acc[mi][ni][2] = 0.f; acc[mi][ni][3] = 0.f;
                    }
                }
            }
        }
    }

#pragma unroll
    for (int mi = 0; mi < 2; mi++) {
        int ra = n0 + wm * 32 + mi * 16 + g;
#pragma unroll
        for (int ni = 0; ni < 8; ni++) {
            int c0 = wn * 64 + ni * 8 + tg * 2;
            float b0 = 6.0f * bc[c0];
            float b1 = 6.0f * bc[c0 + 1];
            if (ra < NN) {
                float2 v = make_float2(facc[mi][ni][0] + b0, facc[mi][ni][1] + b1);
                *reinterpret_cast<float2*>(&out[(size_t)ra * FF + c0]) = v;
            }
            if (ra + 8 < NN) {
                float2 v = make_float2(facc[mi][ni][2] + b0, facc[mi][ni][3] + b1);
                *reinterpret_cast<float2*>(&out[(size_t)(ra + 8) * FF + c0]) = v;
            }
        }
    }
}

// ---------------- launch ----------------
extern "C" void kernel_launch(void* const* d_in, const int* in_sizes, int n_in,
                              void* d_out, int out_size) {
    const float* node_h = (const float*)d_in[0];
    const float* W      = (const float*)d_in[1];
    const float* att1   = (const float*)d_in[2];
    const float* att2   = (const float*)d_in[3];
    const float* Wc     = (const float*)d_in[4];
    const float* bc     = (const float*)d_in[5];
    const int*   esrc   = (const int*)d_in[6];
    const int*   edst   = (const int*)d_in[7];
    const int*   erel   = (const int*)d_in[8];
    float* out = (float*)d_out;

    static int smem_set = 0;
    const int gemm_smem = (128 * AS_STRIDE + 2 * BS_BUF) * sizeof(float);
    if (!smem_set) {
        cudaFuncSetAttribute(gemm_kernel, cudaFuncAttributeMaxDynamicSharedMemorySize, gemm_smem);
        smem_set = 1;
    }

    const int nblk1 = (SEG + 511) / 512;   // 586

    precompute_kernel<<<RR * FF, 128>>>(W, att1, att2, Wc);
    zero_cnt_kernel<<<(SEG + 255) / 256, 256>>>();
    hist_kernel<<<(EE + 255) / 256, 256>>>(edst, erel);
    scan1_kernel<<<nblk1, 512>>>();
    scan2_kernel<<<1, 1024>>>(nblk1);
    scan3_kernel<<<(SEG + 255) / 256, 256>>>();
    permute_kernel<<<(EE + 255) / 256, 256>>>(esrc, edst, erel);
    gather_attn_kernel<<<NN, 128>>>(node_h);
    gemm_kernel<<<(NN + 127) / 128, 256, gemm_smem>>>(out, bc);

    if (out_size >= NN * FF + RR * FF * FF) {
        cudaMemcpyAsync(out + (size_t)NN * FF, W,
                        sizeof(float) * RR * FF * FF, cudaMemcpyDeviceToDevice, 0);
    }
}

// round 5
// speedup vs baseline: 2.2689x; 1.7376x over previous
#include <cuda_runtime.h>
#include <cuda_fp16.h>
#include <cstdint>

#define NN 50000
#define EE 800000
#define RR 6
#define FF 128
#define SEG (RR * NN)

// ---------------- scratch (static device globals; no allocations) ----------------
__device__ __align__(16) float g_aggN[(size_t)SEG * FF];   // 153.6 MB
__device__ __align__(16) float g_c1[NN * RR];
__device__ __align__(16) float g_c2[NN * RR];
__device__ __align__(16) float g_v1[RR * FF];
__device__ __align__(16) float g_v2[RR * FF];
__device__ __align__(16) __half g_Bh[12 * FF * FF];        // fp16 fused B: [h*6+r][o][k]
__device__ __align__(16) float g_e1[SEG];
__device__ __align__(16) float g_e2[SEG];
__device__ __align__(16) int g_cnt[SEG];
__device__ __align__(16) int g_off[SEG];
__device__ __align__(16) int g_cur[SEG];
__device__ __align__(16) int g_bsum[1024];
__device__ __align__(16) int g_src_sorted[EE];

__device__ __forceinline__ void cpa16(void* dst_smem, const void* src) {
    uint32_t d = (uint32_t)__cvta_generic_to_shared(dst_smem);
    asm volatile("cp.async.cg.shared.global [%0], [%1], 16;" :: "r"(d), "l"(src));
}

// ---------------- K0: precompute v1,v2 and fp16 B = W @ [Wc1^T | Wc2^T] ----------------
__global__ void precompute_kernel(const float* __restrict__ W,
                                  const float* __restrict__ att1,
                                  const float* __restrict__ att2,
                                  const float* __restrict__ Wc) {
    __shared__ float wrow[128];
    __shared__ float red1[128];
    __shared__ float red2[128];
    int rf = blockIdx.x;           // r*128 + f
    int r  = rf >> 7, f = rf & 127;
    int o  = threadIdx.x;
    wrow[o] = W[rf * 128 + o];
    __syncthreads();

    float m1 = 0.f, m2 = 0.f;
    const float* wc = Wc + o * 256;
#pragma unroll 8
    for (int j = 0; j < 128; j++) {
        float w = wrow[j];
        m1 += w * wc[j];
        m2 += w * wc[128 + j];
    }
    // B layout: [h*6+r][o][k=f]
    g_Bh[(size_t)(0 * 6 + r) * (FF * FF) + o * FF + f] = __float2half_rn(m1);
    g_Bh[(size_t)(1 * 6 + r) * (FF * FF) + o * FF + f] = __float2half_rn(m2);

    red1[o] = wrow[o] * att1[o];
    red2[o] = wrow[o] * att2[o];
    __syncthreads();
    for (int s = 64; s > 0; s >>= 1) {
        if (o < s) { red1[o] += red1[o + s]; red2[o] += red2[o + s]; }
        __syncthreads();
    }
    if (o == 0) { g_v1[rf] = red1[0]; g_v2[rf] = red2[0]; }
}

// ---------------- CSR build ----------------
__global__ void zero_cnt_kernel() {
    int i = blockIdx.x * blockDim.x + threadIdx.x;
    if (i < SEG) g_cnt[i] = 0;
}
__global__ void hist_kernel(const int* __restrict__ edst, const int* __restrict__ erel) {
    int i = blockIdx.x * blockDim.x + threadIdx.x;
    if (i >= EE) return;
    atomicAdd(&g_cnt[erel[i] * NN + edst[i]], 1);
}
__global__ void scan1_kernel() {
    __shared__ int sm[512];
    int tid = threadIdx.x;
    int idx = blockIdx.x * 512 + tid;
    int v = (idx < SEG) ? g_cnt[idx] : 0;
    sm[tid] = v;
    __syncthreads();
#pragma unroll
    for (int s = 1; s < 512; s <<= 1) {
        int add = (tid >= s) ? sm[tid - s] : 0;
        __syncthreads();
        sm[tid] += add;
        __syncthreads();
    }
    int incl = sm[tid];
    if (idx < SEG) g_off[idx] = incl - v;
    if (tid == 511) g_bsum[blockIdx.x] = incl;
}
__global__ void scan2_kernel(int nblk) {
    __shared__ int sm[1024];
    int tid = threadIdx.x;
    int v = (tid < nblk) ? g_bsum[tid] : 0;
    sm[tid] = v;
    __syncthreads();
#pragma unroll
    for (int s = 1; s < 1024; s <<= 1) {
        int add = (tid >= s) ? sm[tid - s] : 0;
        __syncthreads();
        sm[tid] += add;
        __syncthreads();
    }
    if (tid < nblk) g_bsum[tid] = sm[tid] - v;
}
__global__ void scan3_kernel() {
    int idx = blockIdx.x * blockDim.x + threadIdx.x;
    if (idx >= SEG) return;
    int o = g_off[idx] + g_bsum[idx >> 9];
    g_off[idx] = o;
    g_cur[idx] = o;
}
__global__ void permute_kernel(const int* __restrict__ esrc,
                               const int* __restrict__ edst,
                               const int* __restrict__ erel) {
    int i = blockIdx.x * blockDim.x + threadIdx.x;
    if (i >= EE) return;
    int key = erel[i] * NN + edst[i];
    int pos = atomicAdd(&g_cur[key], 1);
    g_src_sorted[pos] = esrc[i];
}

// ---------------- gather: one warp per (rel,dst) segment ----------------
__global__ __launch_bounds__(256) void gather_kernel(const float* __restrict__ node_h) {
    int seg = blockIdx.x * 8 + (threadIdx.x >> 5);
    if (seg >= SEG) return;
    int l = threadIdx.x & 31;
    int r = seg / NN;
    int off = g_off[seg];
    int deg = g_cnt[seg];

    const float4* h4 = reinterpret_cast<const float4*>(node_h);
    float4 acc = make_float4(0.f, 0.f, 0.f, 0.f);
    int e = 0;
    for (; e + 2 <= deg; e += 2) {
        int i0 = g_src_sorted[off + e];
        int i1 = g_src_sorted[off + e + 1];
        float4 a = h4[(size_t)i0 * 32 + l];
        float4 b = h4[(size_t)i1 * 32 + l];
        acc.x += a.x + b.x; acc.y += a.y + b.y;
        acc.z += a.z + b.z; acc.w += a.w + b.w;
    }
    if (e < deg) {
        int i0 = g_src_sorted[off + e];
        float4 a = h4[(size_t)i0 * 32 + l];
        acc.x += a.x; acc.y += a.y; acc.z += a.z; acc.w += a.w;
    }
    reinterpret_cast<float4*>(g_aggN)[(size_t)seg * 32 + l] = acc;

    float4 w1 = reinterpret_cast<const float4*>(g_v1)[r * 32 + l];
    float4 w2 = reinterpret_cast<const float4*>(g_v2)[r * 32 + l];
    float p1 = acc.x * w1.x + acc.y * w1.y + acc.z * w1.z + acc.w * w1.w;
    float p2 = acc.x * w2.x + acc.y * w2.y + acc.z * w2.z + acc.w * w2.w;
#pragma unroll
    for (int s = 16; s > 0; s >>= 1) {
        p1 += __shfl_xor_sync(0xffffffffu, p1, s);
        p2 += __shfl_xor_sync(0xffffffffu, p2, s);
    }
    if (l == 0) { g_e1[seg] = p1; g_e2[seg] = p2; }
}

// ---------------- per-node softmax -> c1,c2 ----------------
__global__ void softmax_kernel() {
    int n = blockIdx.x * blockDim.x + threadIdx.x;
    if (n >= NN) return;
    float e1[RR], e2[RR], dg[RR];
#pragma unroll
    for (int r = 0; r < RR; r++) {
        dg[r] = 1.0f + (float)g_cnt[r * NN + n];
        e1[r] = g_e1[r * NN + n] / dg[r];
        e2[r] = g_e2[r * NN + n] / dg[r];
    }
    float m1 = e1[0], m2 = e2[0];
#pragma unroll
    for (int r = 1; r < RR; r++) { m1 = fmaxf(m1, e1[r]); m2 = fmaxf(m2, e2[r]); }
    float s1 = 0.f, s2 = 0.f;
#pragma unroll
    for (int r = 0; r < RR; r++) {
        e1[r] = __expf(e1[r] - m1); s1 += e1[r];
        e2[r] = __expf(e2[r] - m2); s2 += e2[r];
    }
    float i1 = 1.0f / s1, i2 = 1.0f / s2;
#pragma unroll
    for (int r = 0; r < RR; r++) {
        g_c1[n * RR + r] = e1[r] * i1 / dg[r];
        g_c2[n * RR + r] = e2[r] * i2 / dg[r];
    }
}

// ---------------- K4: per-relation fp16 GEMM (m16n8k16) with post-scaled accumulation ----------------
__device__ __forceinline__ void mma16(float d[4], uint32_t a0, uint32_t a1, uint32_t a2, uint32_t a3,
                                      uint32_t b0, uint32_t b1) {
    asm volatile(
        "mma.sync.aligned.m16n8k16.row.col.f32.f16.f16.f32 "
        "{%0,%1,%2,%3},{%4,%5,%6,%7},{%8,%9},{%0,%1,%2,%3};"
        : "+f"(d[0]), "+f"(d[1]), "+f"(d[2]), "+f"(d[3])
        : "r"(a0), "r"(a1), "r"(a2), "r"(a3), "r"(b0), "r"(b1));
}

#define ASTRIDE 136   // fp16 units; 68 words -> bank = (4g+tg+c)%32 conflict-free
#define BSTRIDE 136
#define BS_H (128 * BSTRIDE)
#define GEMM_SMEM ((128 * ASTRIDE + 2 * BS_H) * 2)   // bytes = 104448

__global__ __launch_bounds__(256, 1) void gemm_kernel(float* __restrict__ out,
                                                      const float* __restrict__ bc) {
    extern __shared__ __half smh[];
    __half* As = smh;                      // [128][ASTRIDE]
    __half* Bs = smh + 128 * ASTRIDE;      // [2][128][BSTRIDE]

    int n0 = blockIdx.x * 128;
    int t = threadIdx.x;
    int warp = t >> 5, lane = t & 31;
    int wm = warp >> 1, wn = warp & 1;     // 4x2 warps; warp tile 32 rows x 64 cols
    int g = lane >> 2, tg = lane & 3;

    float facc[2][8][4];
#pragma unroll
    for (int mi = 0; mi < 2; mi++)
#pragma unroll
        for (int ni = 0; ni < 8; ni++)
#pragma unroll
            for (int j = 0; j < 4; j++) facc[mi][ni][j] = 0.f;

    for (int r = 0; r < RR; r++) {
        // ---- cp.async both heads' B_r tiles (64KB): 16 chunks of 16B per thread
        {
#pragma unroll
            for (int j = 0; j < 16; j++) {
                int lin = t + 256 * j;            // 0..4095
                int head = lin >> 11;
                int rowk = lin & 2047;
                int o = rowk >> 4;
                int kc = (rowk & 15) * 8;
                cpa16(Bs + head * BS_H + o * BSTRIDE + kc,
                      g_Bh + (size_t)(head * 6 + r) * (FF * FF) + o * FF + kc);
            }
            asm volatile("cp.async.commit_group;" ::: "memory");
        }
        // ---- convert A tile fp32 -> fp16 (8 chunks of 8 fp16 per thread)
        {
            const float* base = g_aggN + ((size_t)r * NN + n0) * FF;
#pragma unroll
            for (int j = 0; j < 8; j++) {
                int lin = t + 256 * j;            // 0..2047
                int row = lin >> 4;
                int c8 = (lin & 15) * 8;
                __half2 h0, h1, h2, h3;
                if (n0 + row < NN) {
                    const float4* ap = reinterpret_cast<const float4*>(base + (size_t)row * FF + c8);
                    float4 v0 = ap[0], v1 = ap[1];
                    h0 = __floats2half2_rn(v0.x, v0.y);
                    h1 = __floats2half2_rn(v0.z, v0.w);
                    h2 = __floats2half2_rn(v1.x, v1.y);
                    h3 = __floats2half2_rn(v1.z, v1.w);
                } else {
                    h0 = h1 = h2 = h3 = __floats2half2_rn(0.f, 0.f);
                }
                __half2* dp = reinterpret_cast<__half2*>(As + row * ASTRIDE + c8);
                dp[0] = h0; dp[1] = h1; dp[2] = h2; dp[3] = h3;
            }
        }
        asm volatile("cp.async.wait_group 0;" ::: "memory");
        __syncthreads();

        for (int h = 0; h < 2; h++) {
            float acc[2][8][4];
#pragma unroll
            for (int mi = 0; mi < 2; mi++)
#pragma unroll
                for (int ni = 0; ni < 8; ni++)
#pragma unroll
                    for (int j = 0; j < 4; j++) acc[mi][ni][j] = 0.f;

            const __half* Bh = Bs + h * BS_H;
#pragma unroll
            for (int ks = 0; ks < 8; ks++) {
                int k0 = ks * 16;
                uint32_t a[2][4];
#pragma unroll
                for (int mi = 0; mi < 2; mi++) {
                    int row = wm * 32 + mi * 16 + g;
                    const __half* ap = As + row * ASTRIDE + k0 + tg * 2;
                    a[mi][0] = *reinterpret_cast<const uint32_t*>(ap);
                    a[mi][1] = *reinterpret_cast<const uint32_t*>(ap + 8 * ASTRIDE);
                    a[mi][2] = *reinterpret_cast<const uint32_t*>(ap + 8);
                    a[mi][3] = *reinterpret_cast<const uint32_t*>(ap + 8 * ASTRIDE + 8);
                }
                uint32_t b[8][2];
#pragma unroll
                for (int ni = 0; ni < 8; ni++) {
                    int o = wn * 64 + ni * 8 + g;
                    const __half* bp = Bh + o * BSTRIDE + k0 + tg * 2;
                    b[ni][0] = *reinterpret_cast<const uint32_t*>(bp);
                    b[ni][1] = *reinterpret_cast<const uint32_t*>(bp + 8);
                }
#pragma unroll
                for (int mi = 0; mi < 2; mi++)
#pragma unroll
                    for (int ni = 0; ni < 8; ni++)
                        mma16(acc[mi][ni], a[mi][0], a[mi][1], a[mi][2], a[mi][3],
                              b[ni][0], b[ni][1]);
            }

            // fold with per-(node, r) coefficient
            const float* carr = h ? g_c2 : g_c1;
#pragma unroll
            for (int mi = 0; mi < 2; mi++) {
                int ra = n0 + wm * 32 + mi * 16 + g;
                int rb = ra + 8;
                float ca = (ra < NN) ? carr[ra * RR + r] : 0.f;
                float cb = (rb < NN) ? carr[rb * RR + r] : 0.f;
#pragma unroll
                for (int ni = 0; ni < 8; ni++) {
                    facc[mi][ni][0] += ca * acc[mi][ni][0];
                    facc[mi][ni][1] += ca * acc[mi][ni][1];
                    facc[mi][ni][2] += cb * acc[mi][ni][2];
                    facc[mi][ni][3] += cb * acc[mi][ni][3];
                }
            }
        }
        __syncthreads();
    }

    // ---- epilogue: + 6*bc
#pragma unroll
    for (int mi = 0; mi < 2; mi++) {
        int ra = n0 + wm * 32 + mi * 16 + g;
#pragma unroll
        for (int ni = 0; ni < 8; ni++) {
            int c0 = wn * 64 + ni * 8 + tg * 2;
            float b0 = 6.0f * bc[c0];
            float b1 = 6.0f * bc[c0 + 1];
            if (ra < NN) {
                float2 v = make_float2(facc[mi][ni][0] + b0, facc[mi][ni][1] + b1);
                *reinterpret_cast<float2*>(&out[(size_t)ra * FF + c0]) = v;
            }
            if (ra + 8 < NN) {
                float2 v = make_float2(facc[mi][ni][2] + b0, facc[mi][ni][3] + b1);
                *reinterpret_cast<float2*>(&out[(size_t)(ra + 8) * FF + c0]) = v;
            }
        }
    }
}

// ---------------- launch ----------------
extern "C" void kernel_launch(void* const* d_in, const int* in_sizes, int n_in,
                              void* d_out, int out_size) {
    const float* node_h = (const float*)d_in[0];
    const float* W      = (const float*)d_in[1];
    const float* att1   = (const float*)d_in[2];
    const float* att2   = (const float*)d_in[3];
    const float* Wc     = (const float*)d_in[4];
    const float* bc     = (const float*)d_in[5];
    const int*   esrc   = (const int*)d_in[6];
    const int*   edst   = (const int*)d_in[7];
    const int*   erel   = (const int*)d_in[8];
    float* out = (float*)d_out;

    static int smem_set = 0;
    if (!smem_set) {
        cudaFuncSetAttribute(gemm_kernel, cudaFuncAttributeMaxDynamicSharedMemorySize, GEMM_SMEM);
        smem_set = 1;
    }

    const int nblk1 = (SEG + 511) / 512;

    precompute_kernel<<<RR * FF, 128>>>(W, att1, att2, Wc);
    zero_cnt_kernel<<<(SEG + 255) / 256, 256>>>();
    hist_kernel<<<(EE + 255) / 256, 256>>>(edst, erel);
    scan1_kernel<<<nblk1, 512>>>();
    scan2_kernel<<<1, 1024>>>(nblk1);
    scan3_kernel<<<(SEG + 255) / 256, 256>>>();
    permute_kernel<<<(EE + 255) / 256, 256>>>(esrc, edst, erel);
    gather_kernel<<<(SEG + 7) / 8, 256>>>(node_h);
    softmax_kernel<<<(NN + 255) / 256, 256>>>();
    gemm_kernel<<<(NN + 127) / 128, 256, GEMM_SMEM>>>(out, bc);

    if (out_size >= NN * FF + RR * FF * FF) {
        cudaMemcpyAsync(out + (size_t)NN * FF, W,
                        sizeof(float) * RR * FF * FF, cudaMemcpyDeviceToDevice, 0);
    }
}

// round 6
// speedup vs baseline: 3.9920x; 1.7594x over previous
#include <cuda_runtime.h>
#include <cuda_fp16.h>
#include <cstdint>

#define NN 50000
#define EE 800000
#define RR 6
#define FF 128
#define SEG (RR * NN)

// ---------------- scratch (static device globals; no allocations) ----------------
__device__ __align__(16) __half g_aggH[(size_t)SEG * FF];  // 76.8 MB fp16 agg
__device__ __align__(16) float g_c1[NN * RR];
__device__ __align__(16) float g_c2[NN * RR];
__device__ __align__(16) float g_v1[RR * FF];
__device__ __align__(16) float g_v2[RR * FF];
__device__ __align__(16) __half g_Wh[RR * FF * FF];        // [r][o][f] = W[r][f][o] fp16
__device__ __align__(16) __half g_Wc1h[FF * FF];           // [o][k] fp16
__device__ __align__(16) __half g_Wc2h[FF * FF];
__device__ __align__(16) float g_e1[SEG];
__device__ __align__(16) float g_e2[SEG];
__device__ __align__(16) int g_cnt[SEG];
__device__ __align__(16) int g_off[SEG];
__device__ __align__(16) int g_cur[SEG];
__device__ __align__(16) int g_bsum[1024];
__device__ __align__(16) int g_src_sorted[EE];

__device__ __forceinline__ void cpa16(void* dst_smem, const void* src) {
    uint32_t d = (uint32_t)__cvta_generic_to_shared(dst_smem);
    asm volatile("cp.async.cg.shared.global [%0], [%1], 16;" :: "r"(d), "l"(src));
}

// ---------------- K0: precompute v1,v2 and fp16 W^T per relation ----------------
__global__ void precompute_kernel(const float* __restrict__ W,
                                  const float* __restrict__ att1,
                                  const float* __restrict__ att2) {
    __shared__ float wrow[128];
    __shared__ float red1[128];
    __shared__ float red2[128];
    int rf = blockIdx.x;           // r*128 + f
    int r  = rf >> 7, f = rf & 127;
    int o  = threadIdx.x;
    float w = W[rf * 128 + o];
    wrow[o] = w;
    // g_Wh[r][o][f] = W[r][f][o]
    g_Wh[(size_t)r * (FF * FF) + o * FF + f] = __float2half_rn(w);

    red1[o] = w * att1[o];
    red2[o] = w * att2[o];
    __syncthreads();
    for (int s = 64; s > 0; s >>= 1) {
        if (o < s) { red1[o] += red1[o + s]; red2[o] += red2[o + s]; }
        __syncthreads();
    }
    if (o == 0) { g_v1[rf] = red1[0]; g_v2[rf] = red2[0]; }
}

__global__ void wc_convert_kernel(const float* __restrict__ Wc) {
    int o = blockIdx.x, k = threadIdx.x;
    g_Wc1h[o * FF + k] = __float2half_rn(Wc[o * 256 + k]);
    g_Wc2h[o * FF + k] = __float2half_rn(Wc[o * 256 + 128 + k]);
}

// ---------------- CSR build ----------------
__global__ void zero_cnt_kernel() {
    int i = blockIdx.x * blockDim.x + threadIdx.x;
    if (i < SEG) g_cnt[i] = 0;
}
__global__ void hist_kernel(const int* __restrict__ edst, const int* __restrict__ erel) {
    int i = blockIdx.x * blockDim.x + threadIdx.x;
    if (i >= EE) return;
    atomicAdd(&g_cnt[erel[i] * NN + edst[i]], 1);
}
__global__ void scan1_kernel() {
    __shared__ int sm[512];
    int tid = threadIdx.x;
    int idx = blockIdx.x * 512 + tid;
    int v = (idx < SEG) ? g_cnt[idx] : 0;
    sm[tid] = v;
    __syncthreads();
#pragma unroll
    for (int s = 1; s < 512; s <<= 1) {
        int add = (tid >= s) ? sm[tid - s] : 0;
        __syncthreads();
        sm[tid] += add;
        __syncthreads();
    }
    int incl = sm[tid];
    if (idx < SEG) g_off[idx] = incl - v;
    if (tid == 511) g_bsum[blockIdx.x] = incl;
}
__global__ void scan2_kernel(int nblk) {
    __shared__ int sm[1024];
    int tid = threadIdx.x;
    int v = (tid < nblk) ? g_bsum[tid] : 0;
    sm[tid] = v;
    __syncthreads();
#pragma unroll
    for (int s = 1; s < 1024; s <<= 1) {
        int add = (tid >= s) ? sm[tid - s] : 0;
        __syncthreads();
        sm[tid] += add;
        __syncthreads();
    }
    if (tid < nblk) g_bsum[tid] = sm[tid] - v;
}
__global__ void scan3_kernel() {
    int idx = blockIdx.x * blockDim.x + threadIdx.x;
    if (idx >= SEG) return;
    int o = g_off[idx] + g_bsum[idx >> 9];
    g_off[idx] = o;
    g_cur[idx] = o;
}
__global__ void permute_kernel(const int* __restrict__ esrc,
                               const int* __restrict__ edst,
                               const int* __restrict__ erel) {
    int i = blockIdx.x * blockDim.x + threadIdx.x;
    if (i >= EE) return;
    int key = erel[i] * NN + edst[i];
    int pos = atomicAdd(&g_cur[key], 1);
    g_src_sorted[pos] = esrc[i];
}

// ---------------- gather: one warp per (rel,dst) segment; fp16 output ----------------
__global__ __launch_bounds__(256) void gather_kernel(const float* __restrict__ node_h) {
    int seg = blockIdx.x * 8 + (threadIdx.x >> 5);
    if (seg >= SEG) return;
    int l = threadIdx.x & 31;
    int r = seg / NN;
    int off = g_off[seg];
    int deg = g_cnt[seg];

    const float4* h4 = reinterpret_cast<const float4*>(node_h);
    float4 acc = make_float4(0.f, 0.f, 0.f, 0.f);
    int e = 0;
    for (; e + 2 <= deg; e += 2) {
        int i0 = g_src_sorted[off + e];
        int i1 = g_src_sorted[off + e + 1];
        float4 a = h4[(size_t)i0 * 32 + l];
        float4 b = h4[(size_t)i1 * 32 + l];
        acc.x += a.x + b.x; acc.y += a.y + b.y;
        acc.z += a.z + b.z; acc.w += a.w + b.w;
    }
    if (e < deg) {
        int i0 = g_src_sorted[off + e];
        float4 a = h4[(size_t)i0 * 32 + l];
        acc.x += a.x; acc.y += a.y; acc.z += a.z; acc.w += a.w;
    }

    __half2 h01 = __floats2half2_rn(acc.x, acc.y);
    __half2 h23 = __floats2half2_rn(acc.z, acc.w);
    uint2 packed;
    packed.x = *reinterpret_cast<uint32_t*>(&h01);
    packed.y = *reinterpret_cast<uint32_t*>(&h23);
    reinterpret_cast<uint2*>(g_aggH)[(size_t)seg * 32 + l] = packed;

    float4 w1 = reinterpret_cast<const float4*>(g_v1)[r * 32 + l];
    float4 w2 = reinterpret_cast<const float4*>(g_v2)[r * 32 + l];
    float p1 = acc.x * w1.x + acc.y * w1.y + acc.z * w1.z + acc.w * w1.w;
    float p2 = acc.x * w2.x + acc.y * w2.y + acc.z * w2.z + acc.w * w2.w;
#pragma unroll
    for (int s = 16; s > 0; s >>= 1) {
        p1 += __shfl_xor_sync(0xffffffffu, p1, s);
        p2 += __shfl_xor_sync(0xffffffffu, p2, s);
    }
    if (l == 0) { g_e1[seg] = p1; g_e2[seg] = p2; }
}

// ---------------- per-node softmax -> c1,c2 ----------------
__global__ void softmax_kernel() {
    int n = blockIdx.x * blockDim.x + threadIdx.x;
    if (n >= NN) return;
    float e1[RR], e2[RR], dg[RR];
#pragma unroll
    for (int r = 0; r < RR; r++) {
        dg[r] = 1.0f + (float)g_cnt[r * NN + n];
        e1[r] = g_e1[r * NN + n] / dg[r];
        e2[r] = g_e2[r * NN + n] / dg[r];
    }
    float m1 = e1[0], m2 = e2[0];
#pragma unroll
    for (int r = 1; r < RR; r++) { m1 = fmaxf(m1, e1[r]); m2 = fmaxf(m2, e2[r]); }
    float s1 = 0.f, s2 = 0.f;
#pragma unroll
    for (int r = 0; r < RR; r++) {
        e1[r] = __expf(e1[r] - m1); s1 += e1[r];
        e2[r] = __expf(e2[r] - m2); s2 += e2[r];
    }
    float i1 = 1.0f / s1, i2 = 1.0f / s2;
#pragma unroll
    for (int r = 0; r < RR; r++) {
        g_c1[n * RR + r] = e1[r] * i1 / dg[r];
        g_c2[n * RR + r] = e2[r] * i2 / dg[r];
    }
}

// ---------------- K4: fused factored GEMM ----------------
// Stage 1 per r: P_r = aggH[r] @ Wh[r]  (64x128, K=128);  Y += c1*P_r, Z += c2*P_r
// Stage 2: out = Y@Wc1^T + Z@Wc2^T + 6*bc
__device__ __forceinline__ void mma16(float d[4], uint32_t a0, uint32_t a1, uint32_t a2, uint32_t a3,
                                      uint32_t b0, uint32_t b1) {
    asm volatile(
        "mma.sync.aligned.m16n8k16.row.col.f32.f16.f16.f32 "
        "{%0,%1,%2,%3},{%4,%5,%6,%7},{%8,%9},{%0,%1,%2,%3};"
        : "+f"(d[0]), "+f"(d[1]), "+f"(d[2]), "+f"(d[3])
        : "r"(a0), "r"(a1), "r"(a2), "r"(a3), "r"(b0), "r"(b1));
}

#define STR 136
#define AH_OFF 0
#define BW_OFF (2 * 64 * STR)
#define YZ_OFF (BW_OFF + 2 * 128 * STR)
#define WC2_OFF (YZ_OFF + 2 * 64 * STR)
#define GEMM_SMEM ((WC2_OFF + 128 * STR) * 2)   // 174080 bytes

__global__ __launch_bounds__(256, 1) void gemm_kernel(float* __restrict__ out,
                                                      const float* __restrict__ bc) {
    extern __shared__ __half sh[];
    __half* Ah   = sh + AH_OFF;    // [2][64][STR]
    __half* Bw   = sh + BW_OFF;    // [2][128][STR]  (stage 6 loads Wc1 into buf 0)
    __half* Yz   = sh + YZ_OFF;    // [2][64][STR]
    __half* Wc2s = sh + WC2_OFF;   // [128][STR]

    int n0 = blockIdx.x * 64;
    int t = threadIdx.x;
    int warp = t >> 5, lane = t & 31;
    int wm = warp >> 2, wn = warp & 3;   // 2x4 warps, warp tile 32 rows x 32 cols
    int g = lane >> 2, tg = lane & 3;

    float P[2][4][4], Y[2][4][4], Z[2][4][4];
#pragma unroll
    for (int mi = 0; mi < 2; mi++)
#pragma unroll
        for (int ni = 0; ni < 4; ni++)
#pragma unroll
            for (int j = 0; j < 4; j++) { P[mi][ni][j] = 0.f; Y[mi][ni][j] = 0.f; Z[mi][ni][j] = 0.f; }

    auto ldstage = [&](int s) {
        if (s < 6) {
            int buf = s & 1;
#pragma unroll
            for (int j = 0; j < 4; j++) {                 // A tile: 64x128 halves
                int lin = t + 256 * j;
                int row = lin >> 4;
                int c8 = (lin & 15) * 8;
                int n = n0 + row;
                if (n >= NN) n = 0;
                cpa16(Ah + buf * 64 * STR + row * STR + c8,
                      g_aggH + ((size_t)s * NN + n) * FF + c8);
            }
#pragma unroll
            for (int j = 0; j < 8; j++) {                 // W tile: 128x128 halves
                int lin = t + 256 * j;
                int o = lin >> 4;
                int c8 = (lin & 15) * 8;
                cpa16(Bw + buf * 128 * STR + o * STR + c8,
                      g_Wh + (size_t)s * (FF * FF) + o * FF + c8);
            }
        } else {
#pragma unroll
            for (int j = 0; j < 8; j++) {                 // Wc1 -> Bw[0]
                int lin = t + 256 * j;
                int o = lin >> 4;
                int c8 = (lin & 15) * 8;
                cpa16(Bw + o * STR + c8, g_Wc1h + o * FF + c8);
            }
#pragma unroll
            for (int j = 0; j < 8; j++) {                 // Wc2 -> Wc2s
                int lin = t + 256 * j;
                int o = lin >> 4;
                int c8 = (lin & 15) * 8;
                cpa16(Wc2s + o * STR + c8, g_Wc2h + o * FF + c8);
            }
        }
        asm volatile("cp.async.commit_group;" ::: "memory");
    };

    auto mmastep = [&](const __half* Abase, const __half* Bbase) {
#pragma unroll
        for (int ks = 0; ks < 8; ks++) {
            int k0 = ks * 16;
            uint32_t a[2][4];
#pragma unroll
            for (int mi = 0; mi < 2; mi++) {
                const __half* ap = Abase + (wm * 32 + mi * 16 + g) * STR + k0 + tg * 2;
                a[mi][0] = *reinterpret_cast<const uint32_t*>(ap);
                a[mi][1] = *reinterpret_cast<const uint32_t*>(ap + 8 * STR);
                a[mi][2] = *reinterpret_cast<const uint32_t*>(ap + 8);
                a[mi][3] = *reinterpret_cast<const uint32_t*>(ap + 8 * STR + 8);
            }
            uint32_t b[4][2];
#pragma unroll
            for (int ni = 0; ni < 4; ni++) {
                const __half* bp = Bbase + (wn * 32 + ni * 8 + g) * STR + k0 + tg * 2;
                b[ni][0] = *reinterpret_cast<const uint32_t*>(bp);
                b[ni][1] = *reinterpret_cast<const uint32_t*>(bp + 8);
            }
#pragma unroll
            for (int mi = 0; mi < 2; mi++)
#pragma unroll
                for (int ni = 0; ni < 4; ni++)
                    mma16(P[mi][ni], a[mi][0], a[mi][1], a[mi][2], a[mi][3],
                          b[ni][0], b[ni][1]);
        }
    };

    ldstage(0);
    ldstage(1);

    for (int s = 0; s < 6; s++) {
        asm volatile("cp.async.wait_group 1;" ::: "memory");
        __syncthreads();
        int buf = s & 1;
        mmastep(Ah + buf * 64 * STR, Bw + buf * 128 * STR);
        // fold P into Y, Z with per-(node, r) coefficients
#pragma unroll
        for (int mi = 0; mi < 2; mi++) {
            int ra = n0 + wm * 32 + mi * 16 + g;
            int rb = ra + 8;
            float c1a = (ra < NN) ? g_c1[ra * RR + s] : 0.f;
            float c1b = (rb < NN) ? g_c1[rb * RR + s] : 0.f;
            float c2a = (ra < NN) ? g_c2[ra * RR + s] : 0.f;
            float c2b = (rb < NN) ? g_c2[rb * RR + s] : 0.f;
#pragma unroll
            for (int ni = 0; ni < 4; ni++) {
                Y[mi][ni][0] += c1a * P[mi][ni][0];
                Y[mi][ni][1] += c1a * P[mi][ni][1];
                Y[mi][ni][2] += c1b * P[mi][ni][2];
                Y[mi][ni][3] += c1b * P[mi][ni][3];
                Z[mi][ni][0] += c2a * P[mi][ni][0];
                Z[mi][ni][1] += c2a * P[mi][ni][1];
                Z[mi][ni][2] += c2b * P[mi][ni][2];
                Z[mi][ni][3] += c2b * P[mi][ni][3];
                P[mi][ni][0] = 0.f; P[mi][ni][1] = 0.f;
                P[mi][ni][2] = 0.f; P[mi][ni][3] = 0.f;
            }
        }
        __syncthreads();
        if (s + 2 <= 6) ldstage(s + 2);
    }

    asm volatile("cp.async.wait_group 0;" ::: "memory");

    // store Y,Z (fp16) to smem
#pragma unroll
    for (int mi = 0; mi < 2; mi++) {
        int row = wm * 32 + mi * 16 + g;
#pragma unroll
        for (int ni = 0; ni < 4; ni++) {
            int col = wn * 32 + ni * 8 + tg * 2;
            *reinterpret_cast<__half2*>(Yz + row * STR + col) =
                __floats2half2_rn(Y[mi][ni][0], Y[mi][ni][1]);
            *reinterpret_cast<__half2*>(Yz + (row + 8) * STR + col) =
                __floats2half2_rn(Y[mi][ni][2], Y[mi][ni][3]);
            *reinterpret_cast<__half2*>(Yz + 64 * STR + row * STR + col) =
                __floats2half2_rn(Z[mi][ni][0], Z[mi][ni][1]);
            *reinterpret_cast<__half2*>(Yz + 64 * STR + (row + 8) * STR + col) =
                __floats2half2_rn(Z[mi][ni][2], Z[mi][ni][3]);
        }
    }
    __syncthreads();

    // stage 2: out = Yh@Wc1^T + Zh@Wc2^T   (P reused as accumulator, already zero)
    mmastep(Yz, Bw);                 // Y @ Wc1^T
    mmastep(Yz + 64 * STR, Wc2s);    // Z @ Wc2^T

    // epilogue: + 6*bc
#pragma unroll
    for (int mi = 0; mi < 2; mi++) {
        int ra = n0 + wm * 32 + mi * 16 + g;
#pragma unroll
        for (int ni = 0; ni < 4; ni++) {
            int col = wn * 32 + ni * 8 + tg * 2;
            float b0 = 6.0f * bc[col];
            float b1 = 6.0f * bc[col + 1];
            if (ra < NN) {
                float2 v = make_float2(P[mi][ni][0] + b0, P[mi][ni][1] + b1);
                *reinterpret_cast<float2*>(&out[(size_t)ra * FF + col]) = v;
            }
            if (ra + 8 < NN) {
                float2 v = make_float2(P[mi][ni][2] + b0, P[mi][ni][3] + b1);
                *reinterpret_cast<float2*>(&out[(size_t)(ra + 8) * FF + col]) = v;
            }
        }
    }
}

// ---------------- launch ----------------
extern "C" void kernel_launch(void* const* d_in, const int* in_sizes, int n_in,
                              void* d_out, int out_size) {
    const float* node_h = (const float*)d_in[0];
    const float* W      = (const float*)d_in[1];
    const float* att1   = (const float*)d_in[2];
    const float* att2   = (const float*)d_in[3];
    const float* Wc     = (const float*)d_in[4];
    const float* bc     = (const float*)d_in[5];
    const int*   esrc   = (const int*)d_in[6];
    const int*   edst   = (const int*)d_in[7];
    const int*   erel   = (const int*)d_in[8];
    float* out = (float*)d_out;

    static int smem_set = 0;
    if (!smem_set) {
        cudaFuncSetAttribute(gemm_kernel, cudaFuncAttributeMaxDynamicSharedMemorySize, GEMM_SMEM);
        smem_set = 1;
    }

    const int nblk1 = (SEG + 511) / 512;

    precompute_kernel<<<RR * FF, 128>>>(W, att1, att2);
    wc_convert_kernel<<<FF, 128>>>(Wc);
    zero_cnt_kernel<<<(SEG + 255) / 256, 256>>>();
    hist_kernel<<<(EE + 255) / 256, 256>>>(edst, erel);
    scan1_kernel<<<nblk1, 512>>>();
    scan2_kernel<<<1, 1024>>>(nblk1);
    scan3_kernel<<<(SEG + 255) / 256, 256>>>();
    permute_kernel<<<(EE + 255) / 256, 256>>>(esrc, edst, erel);
    gather_kernel<<<(SEG + 7) / 8, 256>>>(node_h);
    softmax_kernel<<<(NN + 255) / 256, 256>>>();
    gemm_kernel<<<(NN + 63) / 64, 256, GEMM_SMEM>>>(out, bc);

    if (out_size >= NN * FF + RR * FF * FF) {
        cudaMemcpyAsync(out + (size_t)NN * FF, W,
                        sizeof(float) * RR * FF * FF, cudaMemcpyDeviceToDevice, 0);
    }
}